// round 14
// baseline (speedup 1.0000x reference)
#include <cuda_runtime.h>

#define N_NODES 4096
#define D_DIM   2048
#define B_SAMP  64

#define A_T_C    0.3f
#define DSBETA_C 1e-4f
#define E_B_C    0.5f
#define E_N_C    0.005f      // 0.01 * E_B
#define EPS_DS_C 0.01f

// Persistent state across the sequential scan (allocation-free scratch).
__device__ float g_M[(size_t)N_NODES * D_DIM];
__device__ float g_R[(size_t)N_NODES * D_DIM];
__device__ unsigned long long g_best[B_SAMP];
__device__ int g_nb_word32;   // 1 => neighbors stored as 32-bit words, 0 => bytes

__global__ void reset_best_kernel(const unsigned int* __restrict__ nb) {
    if (threadIdx.x < B_SAMP) g_best[threadIdx.x] = 0ULL;
    if (threadIdx.x == 0) {
        // Bool widened to int32 -> words are 0/1; to float32 -> 0/0x3F800000.
        // Raw byte-bools give random packed words; P(all 256 pass) ~ (1/8)^256.
        int w32 = 1;
        for (int i = 0; i < 256; i++) {
            unsigned v = nb[i];
            if (!(v == 0u || v == 1u || v == 0x3F800000u)) { w32 = 0; break; }
        }
        g_nb_word32 = w32;
    }
}

// Phase A: per-node activation + packed argmax via atomicMax.
// One block per node; 256 threads stream the D=2048 row as float4.
// W and R reads use DEFAULT policy: these are the arrays we want L2-resident.
__global__ __launch_bounds__(256) void act_kernel(const float* __restrict__ x,
                                                  const float* __restrict__ W,
                                                  int t) {
    const int n   = blockIdx.x;
    const int tid = threadIdx.x;
    const float4* Wr = (const float4*)(W   + (size_t)n * D_DIM);
    const float4* Rr = (const float4*)(g_R + (size_t)n * D_DIM);
    const float4* xr = (const float4*)x;

    float dist = 0.f, rsum = 0.f;
#pragma unroll
    for (int k = 0; k < (D_DIM / 4) / 256; k++) {
        int i = k * 256 + tid;
        float4 w  = Wr[i];
        float4 r  = Rr[i];
        float4 xv = __ldg(&xr[i]);
        float d0 = xv.x - w.x, d1 = xv.y - w.y, d2 = xv.z - w.z, d3 = xv.w - w.w;
        dist += r.x * d0 * d0 + r.y * d1 * d1 + r.z * d2 * d2 + r.w * d3 * d3;
        rsum += r.x + r.y + r.z + r.w;
    }
#pragma unroll
    for (int o = 16; o > 0; o >>= 1) {
        dist += __shfl_down_sync(0xffffffffu, dist, o);
        rsum += __shfl_down_sync(0xffffffffu, rsum, o);
    }
    __shared__ float sd[8], sr[8];
    int wrp = tid >> 5, lane = tid & 31;
    if (lane == 0) { sd[wrp] = dist; sr[wrp] = rsum; }
    __syncthreads();
    if (tid == 0) {
        float dt = 0.f, rt = 0.f;
#pragma unroll
        for (int i = 0; i < 8; i++) { dt += sd[i]; rt += sr[i]; }
        float act = rt / (rt + dt + 1e-7f);
        // act > 0 always (R > 0) so the float bit pattern is order-preserving.
        // Low word = 0xFFFFFFFF - n: ties pick the SMALLEST node index
        // (matches jnp.argmax first-occurrence semantics).
        unsigned long long key =
            ((unsigned long long)__float_as_uint(act) << 32) |
            (unsigned long long)(0xFFFFFFFFu - (unsigned)n);
        unsigned long long cur = g_best[t];
        if (key > cur) atomicMax(&g_best[t], key);
    }
}

// Phase B: update winner + neighbors. One block per node; inactive blocks
// early-exit after one neighbor read. M is touched ONLY here and never read
// by act, so it is kept OUT of L2 entirely: __ldcv (fetch from memory, no
// useful allocation) + __stwt (write-through). This caps per-step L2
// allocations at ~64 MB (act's W+R), letting W/R stay resident across steps.
__global__ __launch_bounds__(256) void update_kernel(const float* __restrict__ x,
                                                     float* __restrict__ W,
                                                     const void* __restrict__ nbv,
                                                     int t) {
    const unsigned long long key = g_best[t];
    const float act = __uint_as_float((unsigned)(key >> 32));
    if (!(act >= A_T_C)) return;  // do_upd == false -> whole step is a no-op
    const int winner = (int)(0xFFFFFFFFu - (unsigned)(key & 0xFFFFFFFFu));

    const int n = blockIdx.x;
    float lr;
    if (n == winner) {
        lr = E_B_C;
    } else {
        bool isnb;
        const size_t idx = (size_t)winner * N_NODES + n;
        if (g_nb_word32) {
            isnb = __ldcv((const unsigned int*)nbv + idx) != 0u;
        } else {
            isnb = __ldcv((const unsigned char*)nbv + idx) != 0;
        }
        if (!isnb) return;
        lr = E_N_C;
    }

    const int tid = threadIdx.x;
    float4* Wr = (float4*)(W   + (size_t)n * D_DIM);
    float4* Mr = (float4*)(g_M + (size_t)n * D_DIM);
    float4* Rr = (float4*)(g_R + (size_t)n * D_DIM);
    const float4* xr = (const float4*)x;

    const float c   = lr * DSBETA_C;
    const float omc = 1.0f - c;

    float4 Mn[2], Wn[2];
    float pmax = -1e30f, pmin = 1e30f, psum = 0.f;
#pragma unroll
    for (int k = 0; k < 2; k++) {
        int i = k * 256 + tid;
        float4 w  = Wr[i];
        float4 m  = __ldcv(Mr + i);               // M: bypass L2 retention
        float4 xv = __ldg(&xr[i]);
        float d0 = xv.x - w.x, d1 = xv.y - w.y, d2 = xv.z - w.z, d3 = xv.w - w.w;
        float4 mn;
        mn.x = c * fabsf(d0) + omc * m.x;
        mn.y = c * fabsf(d1) + omc * m.y;
        mn.z = c * fabsf(d2) + omc * m.z;
        mn.w = c * fabsf(d3) + omc * m.w;
        Mn[k] = mn;
        float4 wn;
        wn.x = w.x + lr * d0;
        wn.y = w.y + lr * d1;
        wn.z = w.z + lr * d2;
        wn.w = w.w + lr * d3;
        Wn[k] = wn;
        pmax = fmaxf(pmax, fmaxf(fmaxf(mn.x, mn.y), fmaxf(mn.z, mn.w)));
        pmin = fminf(pmin, fminf(fminf(mn.x, mn.y), fminf(mn.z, mn.w)));
        psum += mn.x + mn.y + mn.z + mn.w;
    }
    // 3-way block reduction (max, min, sum of M_new over the row)
#pragma unroll
    for (int o = 16; o > 0; o >>= 1) {
        pmax = fmaxf(pmax, __shfl_down_sync(0xffffffffu, pmax, o));
        pmin = fminf(pmin, __shfl_down_sync(0xffffffffu, pmin, o));
        psum +=            __shfl_down_sync(0xffffffffu, psum, o);
    }
    __shared__ float smax[8], smin[8], ssum[8];
    __shared__ float s_av, s_den;
    int wrp = tid >> 5, lane = tid & 31;
    if (lane == 0) { smax[wrp] = pmax; smin[wrp] = pmin; ssum[wrp] = psum; }
    __syncthreads();
    if (tid == 0) {
        float mx = -1e30f, mnv = 1e30f, sum = 0.f;
#pragma unroll
        for (int i = 0; i < 8; i++) {
            mx  = fmaxf(mx, smax[i]);
            mnv = fminf(mnv, smin[i]);
            sum += ssum[i];
        }
        s_av  = sum / (float)D_DIM;
        s_den = EPS_DS_C * (mx - mnv);
    }
    __syncthreads();
    const float av  = s_av;
    const float den = s_den;
    const bool  zero = (den == 0.0f);

#pragma unroll
    for (int k = 0; k < 2; k++) {
        int i = k * 256 + tid;
        float4 mn = Mn[k];
        float4 r;
        if (zero) {
            r.x = r.y = r.z = r.w = 1.0f;   // matches reference's NaN->1 path
        } else {
            float a0 = fminf(fmaxf((mn.x - av) / den, -80.0f), 80.0f);
            float a1 = fminf(fmaxf((mn.y - av) / den, -80.0f), 80.0f);
            float a2 = fminf(fmaxf((mn.z - av) / den, -80.0f), 80.0f);
            float a3 = fminf(fmaxf((mn.w - av) / den, -80.0f), 80.0f);
            r.x = 1.0f / (1.0f + expf(a0));
            r.y = 1.0f / (1.0f + expf(a1));
            r.z = 1.0f / (1.0f + expf(a2));
            r.w = 1.0f / (1.0f + expf(a3));
        }
        __stwt(Mr + i, mn);                       // M: write-through, no L2 dirty line
        Rr[i] = r;                                // R/W: default -> stay L2-resident
        Wr[i] = Wn[k];
    }
}

extern "C" void kernel_launch(void* const* d_in, const int* in_sizes, int n_in,
                              void* d_out, int out_size) {
    const float* x          = (const float*)d_in[0];   // [B, D]
    const float* weights    = (const float*)d_in[1];   // [N, D]
    const float* moving_avg = (const float*)d_in[2];   // [N, D]
    const float* relevances = (const float*)d_in[3];   // [N, D]
    // d_in[4] = wins (unused for output)
    const void*  neighbors  = d_in[5];                 // [N, N] bool (width auto-detected)

    float* W = (float*)d_out;

    void *pM = nullptr, *pR = nullptr;
    cudaGetSymbolAddress(&pM, g_M);
    cudaGetSymbolAddress(&pR, g_R);

    const size_t bytes = sizeof(float) * (size_t)N_NODES * D_DIM;
    cudaMemcpyAsync(W,  weights,    bytes, cudaMemcpyDeviceToDevice);
    cudaMemcpyAsync(pM, moving_avg, bytes, cudaMemcpyDeviceToDevice);
    cudaMemcpyAsync(pR, relevances, bytes, cudaMemcpyDeviceToDevice);

    reset_best_kernel<<<1, 64>>>((const unsigned int*)neighbors);

    for (int t = 0; t < B_SAMP; t++) {
        const float* xt = x + (size_t)t * D_DIM;
        act_kernel<<<N_NODES, 256>>>(xt, W, t);
        update_kernel<<<N_NODES, 256>>>(xt, W, neighbors, t);
    }
}

// round 15
// speedup vs baseline: 1.0336x; 1.0336x over previous
#include <cuda_runtime.h>
#include <cuda_bf16.h>

#define N_NODES 4096
#define D_DIM   2048
#define B_SAMP  64

#define A_T_C    0.3f
#define DSBETA_C 1e-4f
#define E_B_C    0.5f
#define E_N_C    0.005f      // 0.01 * E_B
#define EPS_DS_C 0.01f

// Persistent state (allocation-free scratch).
// f32 R is NOT stored: R only feeds activations, which use the bf16 shadows.
__device__ float          g_M [(size_t)N_NODES * D_DIM];
__device__ __nv_bfloat162 g_Wh[(size_t)N_NODES * D_DIM / 2];   // bf16 shadow of W
__device__ __nv_bfloat162 g_Rh[(size_t)N_NODES * D_DIM / 2];   // bf16 shadow of R
__device__ unsigned long long g_best[B_SAMP];
__device__ int g_nb_word32;   // 1 => neighbors stored as 32-bit words, 0 => bytes

__global__ void reset_best_kernel(const unsigned int* __restrict__ nb) {
    if (threadIdx.x < B_SAMP) g_best[threadIdx.x] = 0ULL;
    if (threadIdx.x == 0) {
        // Bool widened to int32 -> words are 0/1; to float32 -> 0/0x3F800000.
        // Raw byte-bools give random packed words; P(all 256 pass) ~ (1/8)^256.
        int w32 = 1;
        for (int i = 0; i < 256; i++) {
            unsigned v = nb[i];
            if (!(v == 0u || v == 1u || v == 0x3F800000u)) { w32 = 0; break; }
        }
        g_nb_word32 = w32;
    }
}

// Convert initial W / R (f32) into the bf16 shadow arrays.
__global__ __launch_bounds__(256) void conv_kernel(const float* __restrict__ Wf,
                                                   const float* __restrict__ Rf) {
    const size_t i = (size_t)blockIdx.x * 256 + threadIdx.x;   // float4 index
    float4 w = ((const float4*)Wf)[i];
    float4 r = ((const float4*)Rf)[i];
    g_Wh[2 * i]     = __floats2bfloat162_rn(w.x, w.y);
    g_Wh[2 * i + 1] = __floats2bfloat162_rn(w.z, w.w);
    g_Rh[2 * i]     = __floats2bfloat162_rn(r.x, r.y);
    g_Rh[2 * i + 1] = __floats2bfloat162_rn(r.z, r.w);
}

// Phase A: activation from bf16 shadows (half the bytes of f32 R+W).
// One block per node; 256 threads x 8 elements = D=2048.
__global__ __launch_bounds__(256) void act_kernel(const float* __restrict__ x,
                                                  int t) {
    const int n   = blockIdx.x;
    const int tid = threadIdx.x;
    const uint4* Whr = (const uint4*)(g_Wh + (size_t)n * (D_DIM / 2));  // 8 bf16 / uint4
    const uint4* Rhr = (const uint4*)(g_Rh + (size_t)n * (D_DIM / 2));
    const float4* xr = (const float4*)x;

    uint4 wv = Whr[tid];
    uint4 rv = Rhr[tid];
    float4 x0 = __ldg(&xr[2 * tid]);
    float4 x1 = __ldg(&xr[2 * tid + 1]);

    float dist = 0.f, rsum = 0.f;
    {
        float2 w0 = __bfloat1622float2(*(const __nv_bfloat162*)&wv.x);
        float2 w1 = __bfloat1622float2(*(const __nv_bfloat162*)&wv.y);
        float2 w2 = __bfloat1622float2(*(const __nv_bfloat162*)&wv.z);
        float2 w3 = __bfloat1622float2(*(const __nv_bfloat162*)&wv.w);
        float2 r0 = __bfloat1622float2(*(const __nv_bfloat162*)&rv.x);
        float2 r1 = __bfloat1622float2(*(const __nv_bfloat162*)&rv.y);
        float2 r2 = __bfloat1622float2(*(const __nv_bfloat162*)&rv.z);
        float2 r3 = __bfloat1622float2(*(const __nv_bfloat162*)&rv.w);
        float d;
        d = x0.x - w0.x; dist += r0.x * d * d;
        d = x0.y - w0.y; dist += r0.y * d * d;
        d = x0.z - w1.x; dist += r1.x * d * d;
        d = x0.w - w1.y; dist += r1.y * d * d;
        d = x1.x - w2.x; dist += r2.x * d * d;
        d = x1.y - w2.y; dist += r2.y * d * d;
        d = x1.z - w3.x; dist += r3.x * d * d;
        d = x1.w - w3.y; dist += r3.y * d * d;
        rsum += r0.x + r0.y + r1.x + r1.y + r2.x + r2.y + r3.x + r3.y;
    }
#pragma unroll
    for (int o = 16; o > 0; o >>= 1) {
        dist += __shfl_down_sync(0xffffffffu, dist, o);
        rsum += __shfl_down_sync(0xffffffffu, rsum, o);
    }
    __shared__ float sd[8], sr[8];
    int wrp = tid >> 5, lane = tid & 31;
    if (lane == 0) { sd[wrp] = dist; sr[wrp] = rsum; }
    __syncthreads();
    if (tid == 0) {
        float dt = 0.f, rt = 0.f;
#pragma unroll
        for (int i = 0; i < 8; i++) { dt += sd[i]; rt += sr[i]; }
        float act = rt / (rt + dt + 1e-7f);
        // act > 0 so the float bit pattern is order-preserving. Low word =
        // 0xFFFFFFFF - n: ties pick the SMALLEST node index (jnp.argmax
        // first-occurrence semantics).
        unsigned long long key =
            ((unsigned long long)__float_as_uint(act) << 32) |
            (unsigned long long)(0xFFFFFFFFu - (unsigned)n);
        unsigned long long cur = g_best[t];
        if (key > cur) atomicMax(&g_best[t], key);
    }
}

// Phase B: update winner + neighbors with EXACT f32 arithmetic (identical to
// the reference); additionally refresh the bf16 shadows for the next act.
__global__ __launch_bounds__(256) void update_kernel(const float* __restrict__ x,
                                                     float* __restrict__ W,
                                                     const void* __restrict__ nbv,
                                                     int t) {
    const unsigned long long key = g_best[t];
    const float act = __uint_as_float((unsigned)(key >> 32));
    if (!(act >= A_T_C)) return;  // do_upd == false -> whole step is a no-op
    const int winner = (int)(0xFFFFFFFFu - (unsigned)(key & 0xFFFFFFFFu));

    const int n = blockIdx.x;
    float lr;
    if (n == winner) {
        lr = E_B_C;
    } else {
        bool isnb;
        const size_t idx = (size_t)winner * N_NODES + n;
        if (g_nb_word32) {
            isnb = __ldcs((const unsigned int*)nbv + idx) != 0u;
        } else {
            isnb = __ldcs((const unsigned char*)nbv + idx) != 0;
        }
        if (!isnb) return;
        lr = E_N_C;
    }

    const int tid = threadIdx.x;
    float4* Wr = (float4*)(W   + (size_t)n * D_DIM);
    float4* Mr = (float4*)(g_M + (size_t)n * D_DIM);
    __nv_bfloat162* Whr = g_Wh + (size_t)n * (D_DIM / 2);
    __nv_bfloat162* Rhr = g_Rh + (size_t)n * (D_DIM / 2);
    const float4* xr = (const float4*)x;

    const float c   = lr * DSBETA_C;
    const float omc = 1.0f - c;

    float4 Mn[2], Wn[2];
    float pmax = -1e30f, pmin = 1e30f, psum = 0.f;
#pragma unroll
    for (int k = 0; k < 2; k++) {
        int i = k * 256 + tid;
        float4 w  = Wr[i];
        float4 m  = __ldcs(Mr + i);               // M: evict-first (streamed)
        float4 xv = __ldg(&xr[i]);
        float d0 = xv.x - w.x, d1 = xv.y - w.y, d2 = xv.z - w.z, d3 = xv.w - w.w;
        float4 mn;
        mn.x = c * fabsf(d0) + omc * m.x;
        mn.y = c * fabsf(d1) + omc * m.y;
        mn.z = c * fabsf(d2) + omc * m.z;
        mn.w = c * fabsf(d3) + omc * m.w;
        Mn[k] = mn;
        float4 wn;
        wn.x = w.x + lr * d0;
        wn.y = w.y + lr * d1;
        wn.z = w.z + lr * d2;
        wn.w = w.w + lr * d3;
        Wn[k] = wn;
        pmax = fmaxf(pmax, fmaxf(fmaxf(mn.x, mn.y), fmaxf(mn.z, mn.w)));
        pmin = fminf(pmin, fminf(fminf(mn.x, mn.y), fminf(mn.z, mn.w)));
        psum += mn.x + mn.y + mn.z + mn.w;
    }
    // 3-way block reduction (max, min, sum of M_new over the row)
#pragma unroll
    for (int o = 16; o > 0; o >>= 1) {
        pmax = fmaxf(pmax, __shfl_down_sync(0xffffffffu, pmax, o));
        pmin = fminf(pmin, __shfl_down_sync(0xffffffffu, pmin, o));
        psum +=            __shfl_down_sync(0xffffffffu, psum, o);
    }
    __shared__ float smax[8], smin[8], ssum[8];
    __shared__ float s_av, s_den;
    int wrp = tid >> 5, lane = tid & 31;
    if (lane == 0) { smax[wrp] = pmax; smin[wrp] = pmin; ssum[wrp] = psum; }
    __syncthreads();
    if (tid == 0) {
        float mx = -1e30f, mnv = 1e30f, sum = 0.f;
#pragma unroll
        for (int i = 0; i < 8; i++) {
            mx  = fmaxf(mx, smax[i]);
            mnv = fminf(mnv, smin[i]);
            sum += ssum[i];
        }
        s_av  = sum / (float)D_DIM;
        s_den = EPS_DS_C * (mx - mnv);
    }
    __syncthreads();
    const float av  = s_av;
    const float den = s_den;
    const bool  zero = (den == 0.0f);

#pragma unroll
    for (int k = 0; k < 2; k++) {
        int i = k * 256 + tid;
        float4 mn = Mn[k];
        float4 r;
        if (zero) {
            r.x = r.y = r.z = r.w = 1.0f;   // matches reference's NaN->1 path
        } else {
            float a0 = fminf(fmaxf((mn.x - av) / den, -80.0f), 80.0f);
            float a1 = fminf(fmaxf((mn.y - av) / den, -80.0f), 80.0f);
            float a2 = fminf(fmaxf((mn.z - av) / den, -80.0f), 80.0f);
            float a3 = fminf(fmaxf((mn.w - av) / den, -80.0f), 80.0f);
            r.x = 1.0f / (1.0f + expf(a0));
            r.y = 1.0f / (1.0f + expf(a1));
            r.z = 1.0f / (1.0f + expf(a2));
            r.w = 1.0f / (1.0f + expf(a3));
        }
        __stcs(Mr + i, mn);                       // M: evict-first
        float4 wn = Wn[k];
        Wr[i] = wn;                               // exact f32 W (the output)
        Whr[2 * i]     = __floats2bfloat162_rn(wn.x, wn.y);
        Whr[2 * i + 1] = __floats2bfloat162_rn(wn.z, wn.w);
        Rhr[2 * i]     = __floats2bfloat162_rn(r.x, r.y);
        Rhr[2 * i + 1] = __floats2bfloat162_rn(r.z, r.w);
    }
}

extern "C" void kernel_launch(void* const* d_in, const int* in_sizes, int n_in,
                              void* d_out, int out_size) {
    const float* x          = (const float*)d_in[0];   // [B, D]
    const float* weights    = (const float*)d_in[1];   // [N, D]
    const float* moving_avg = (const float*)d_in[2];   // [N, D]
    const float* relevances = (const float*)d_in[3];   // [N, D]
    // d_in[4] = wins (unused for output)
    const void*  neighbors  = d_in[5];                 // [N, N] bool (width auto-detected)

    float* W = (float*)d_out;

    void* pM = nullptr;
    cudaGetSymbolAddress(&pM, g_M);

    const size_t bytes = sizeof(float) * (size_t)N_NODES * D_DIM;
    cudaMemcpyAsync(W,  weights,    bytes, cudaMemcpyDeviceToDevice);
    cudaMemcpyAsync(pM, moving_avg, bytes, cudaMemcpyDeviceToDevice);

    reset_best_kernel<<<1, 64>>>((const unsigned int*)neighbors);
    conv_kernel<<<(N_NODES * D_DIM / 4) / 256, 256>>>(weights, relevances);

    for (int t = 0; t < B_SAMP; t++) {
        const float* xt = x + (size_t)t * D_DIM;
        act_kernel<<<N_NODES, 256>>>(xt, t);
        update_kernel<<<N_NODES, 256>>>(xt, W, neighbors, t);
    }
}

// round 16
// speedup vs baseline: 1.1130x; 1.0768x over previous
#include <cuda_runtime.h>
#include <cuda_bf16.h>

#define N_NODES 4096
#define D_DIM   2048
#define B_SAMP  64

#define A_T_C    0.3f
#define DSBETA_C 1e-4f
#define E_B_C    0.5f
#define E_N_C    0.005f      // 0.01 * E_B
#define EPS_DS_C 0.01f

// Persistent state (allocation-free scratch).
// f32 R is NOT stored: R only feeds activations, which use the bf16 shadows.
__device__ float          g_M [(size_t)N_NODES * D_DIM];
__device__ __nv_bfloat162 g_Wh[(size_t)N_NODES * D_DIM / 2];   // bf16 shadow of W
__device__ __nv_bfloat162 g_Rh[(size_t)N_NODES * D_DIM / 2];   // bf16 shadow of R
__device__ unsigned long long g_best[B_SAMP];
__device__ int g_nb_word32;   // 1 => neighbors stored as 32-bit words, 0 => bytes

__global__ void reset_best_kernel(const unsigned int* __restrict__ nb) {
    if (threadIdx.x < B_SAMP) g_best[threadIdx.x] = 0ULL;
    if (threadIdx.x == 0) {
        // Bool widened to int32 -> words are 0/1; to float32 -> 0/0x3F800000.
        // Raw byte-bools give random packed words; P(all 256 pass) ~ (1/8)^256.
        int w32 = 1;
        for (int i = 0; i < 256; i++) {
            unsigned v = nb[i];
            if (!(v == 0u || v == 1u || v == 0x3F800000u)) { w32 = 0; break; }
        }
        g_nb_word32 = w32;
    }
}

// Convert initial W / R (f32) into the bf16 shadow arrays.
__global__ __launch_bounds__(256) void conv_kernel(const float* __restrict__ Wf,
                                                   const float* __restrict__ Rf) {
    const size_t i = (size_t)blockIdx.x * 256 + threadIdx.x;   // float4 index
    float4 w = ((const float4*)Wf)[i];
    float4 r = ((const float4*)Rf)[i];
    g_Wh[2 * i]     = __floats2bfloat162_rn(w.x, w.y);
    g_Wh[2 * i + 1] = __floats2bfloat162_rn(w.z, w.w);
    g_Rh[2 * i]     = __floats2bfloat162_rn(r.x, r.y);
    g_Rh[2 * i + 1] = __floats2bfloat162_rn(r.z, r.w);
}

// Phase A: activation from bf16 shadows (half the bytes of f32 R+W).
// One block per node; 256 threads x 8 elements = D=2048.
__global__ __launch_bounds__(256) void act_kernel(const float* __restrict__ x,
                                                  int t) {
    const int n   = blockIdx.x;
    const int tid = threadIdx.x;
    const uint4* Whr = (const uint4*)(g_Wh + (size_t)n * (D_DIM / 2));  // 8 bf16 / uint4
    const uint4* Rhr = (const uint4*)(g_Rh + (size_t)n * (D_DIM / 2));
    const float4* xr = (const float4*)x;

    uint4 wv = Whr[tid];
    uint4 rv = Rhr[tid];
    float4 x0 = __ldg(&xr[2 * tid]);
    float4 x1 = __ldg(&xr[2 * tid + 1]);

    float dist = 0.f, rsum = 0.f;
    {
        float2 w0 = __bfloat1622float2(*(const __nv_bfloat162*)&wv.x);
        float2 w1 = __bfloat1622float2(*(const __nv_bfloat162*)&wv.y);
        float2 w2 = __bfloat1622float2(*(const __nv_bfloat162*)&wv.z);
        float2 w3 = __bfloat1622float2(*(const __nv_bfloat162*)&wv.w);
        float2 r0 = __bfloat1622float2(*(const __nv_bfloat162*)&rv.x);
        float2 r1 = __bfloat1622float2(*(const __nv_bfloat162*)&rv.y);
        float2 r2 = __bfloat1622float2(*(const __nv_bfloat162*)&rv.z);
        float2 r3 = __bfloat1622float2(*(const __nv_bfloat162*)&rv.w);
        float d;
        d = x0.x - w0.x; dist += r0.x * d * d;
        d = x0.y - w0.y; dist += r0.y * d * d;
        d = x0.z - w1.x; dist += r1.x * d * d;
        d = x0.w - w1.y; dist += r1.y * d * d;
        d = x1.x - w2.x; dist += r2.x * d * d;
        d = x1.y - w2.y; dist += r2.y * d * d;
        d = x1.z - w3.x; dist += r3.x * d * d;
        d = x1.w - w3.y; dist += r3.y * d * d;
        rsum += r0.x + r0.y + r1.x + r1.y + r2.x + r2.y + r3.x + r3.y;
    }
#pragma unroll
    for (int o = 16; o > 0; o >>= 1) {
        dist += __shfl_down_sync(0xffffffffu, dist, o);
        rsum += __shfl_down_sync(0xffffffffu, rsum, o);
    }
    __shared__ float sd[8], sr[8];
    int wrp = tid >> 5, lane = tid & 31;
    if (lane == 0) { sd[wrp] = dist; sr[wrp] = rsum; }
    __syncthreads();
    if (tid == 0) {
        float dt = 0.f, rt = 0.f;
#pragma unroll
        for (int i = 0; i < 8; i++) { dt += sd[i]; rt += sr[i]; }
        float act = rt / (rt + dt + 1e-7f);
        // act > 0 so the float bit pattern is order-preserving. Low word =
        // 0xFFFFFFFF - n: ties pick the SMALLEST node index (jnp.argmax
        // first-occurrence semantics).
        unsigned long long key =
            ((unsigned long long)__float_as_uint(act) << 32) |
            (unsigned long long)(0xFFFFFFFFu - (unsigned)n);
        unsigned long long cur = g_best[t];
        if (key > cur) atomicMax(&g_best[t], key);
    }
}

// Phase B: update winner + neighbors with EXACT f32 arithmetic.
// 128 threads/block (4 warps) -> 16 blocks/SM resident -> half the waves of
// the 256-thread version; W (f32 + bf16 shadow) is written in phase 1, before
// the block reduction, shortening the post-reduction critical path.
__global__ __launch_bounds__(128) void update_kernel(const float* __restrict__ x,
                                                     float* __restrict__ W,
                                                     const void* __restrict__ nbv,
                                                     int t) {
    const unsigned long long key = g_best[t];
    const float act = __uint_as_float((unsigned)(key >> 32));
    if (!(act >= A_T_C)) return;  // do_upd == false -> whole step is a no-op
    const int winner = (int)(0xFFFFFFFFu - (unsigned)(key & 0xFFFFFFFFu));

    const int n = blockIdx.x;
    float lr;
    if (n == winner) {
        lr = E_B_C;
    } else {
        bool isnb;
        const size_t idx = (size_t)winner * N_NODES + n;
        if (g_nb_word32) {
            isnb = __ldcs((const unsigned int*)nbv + idx) != 0u;
        } else {
            isnb = __ldcs((const unsigned char*)nbv + idx) != 0;
        }
        if (!isnb) return;
        lr = E_N_C;
    }

    const int tid = threadIdx.x;
    float4* Wr = (float4*)(W   + (size_t)n * D_DIM);
    float4* Mr = (float4*)(g_M + (size_t)n * D_DIM);
    __nv_bfloat162* Whr = g_Wh + (size_t)n * (D_DIM / 2);
    __nv_bfloat162* Rhr = g_Rh + (size_t)n * (D_DIM / 2);
    const float4* xr = (const float4*)x;

    const float c   = lr * DSBETA_C;
    const float omc = 1.0f - c;

    float4 Mn[4];
    float pmax = -1e30f, pmin = 1e30f, psum = 0.f;
#pragma unroll
    for (int k = 0; k < 4; k++) {
        int i = k * 128 + tid;
        float4 w  = Wr[i];
        float4 m  = __ldcs(Mr + i);               // M: evict-first (streamed)
        float4 xv = __ldg(&xr[i]);
        float d0 = xv.x - w.x, d1 = xv.y - w.y, d2 = xv.z - w.z, d3 = xv.w - w.w;
        float4 mn;
        mn.x = c * fabsf(d0) + omc * m.x;
        mn.y = c * fabsf(d1) + omc * m.y;
        mn.z = c * fabsf(d2) + omc * m.z;
        mn.w = c * fabsf(d3) + omc * m.w;
        Mn[k] = mn;
        float4 wn;
        wn.x = w.x + lr * d0;
        wn.y = w.y + lr * d1;
        wn.z = w.z + lr * d2;
        wn.w = w.w + lr * d3;
        // W does not depend on the reduction: store it now (f32 + bf16 shadow)
        Wr[i] = wn;
        Whr[2 * i]     = __floats2bfloat162_rn(wn.x, wn.y);
        Whr[2 * i + 1] = __floats2bfloat162_rn(wn.z, wn.w);
        pmax = fmaxf(pmax, fmaxf(fmaxf(mn.x, mn.y), fmaxf(mn.z, mn.w)));
        pmin = fminf(pmin, fminf(fminf(mn.x, mn.y), fminf(mn.z, mn.w)));
        psum += mn.x + mn.y + mn.z + mn.w;
    }
    // 3-way block reduction (max, min, sum of M_new over the row), 4 warps
#pragma unroll
    for (int o = 16; o > 0; o >>= 1) {
        pmax = fmaxf(pmax, __shfl_down_sync(0xffffffffu, pmax, o));
        pmin = fminf(pmin, __shfl_down_sync(0xffffffffu, pmin, o));
        psum +=            __shfl_down_sync(0xffffffffu, psum, o);
    }
    __shared__ float smax[4], smin[4], ssum[4];
    __shared__ float s_av, s_den;
    int wrp = tid >> 5, lane = tid & 31;
    if (lane == 0) { smax[wrp] = pmax; smin[wrp] = pmin; ssum[wrp] = psum; }
    __syncthreads();
    if (tid == 0) {
        float mx = -1e30f, mnv = 1e30f, sum = 0.f;
#pragma unroll
        for (int i = 0; i < 4; i++) {
            mx  = fmaxf(mx, smax[i]);
            mnv = fminf(mnv, smin[i]);
            sum += ssum[i];
        }
        s_av  = sum / (float)D_DIM;
        s_den = EPS_DS_C * (mx - mnv);
    }
    __syncthreads();
    const float av  = s_av;
    const float den = s_den;
    const bool  zero = (den == 0.0f);

#pragma unroll
    for (int k = 0; k < 4; k++) {
        int i = k * 128 + tid;
        float4 mn = Mn[k];
        float4 r;
        if (zero) {
            r.x = r.y = r.z = r.w = 1.0f;   // matches reference's NaN->1 path
        } else {
            float a0 = fminf(fmaxf((mn.x - av) / den, -80.0f), 80.0f);
            float a1 = fminf(fmaxf((mn.y - av) / den, -80.0f), 80.0f);
            float a2 = fminf(fmaxf((mn.z - av) / den, -80.0f), 80.0f);
            float a3 = fminf(fmaxf((mn.w - av) / den, -80.0f), 80.0f);
            // __expf error (~2^-21) is far below the bf16 rounding applied to
            // R's shadow, and R is consumed ONLY via the bf16 shadow.
            r.x = 1.0f / (1.0f + __expf(a0));
            r.y = 1.0f / (1.0f + __expf(a1));
            r.z = 1.0f / (1.0f + __expf(a2));
            r.w = 1.0f / (1.0f + __expf(a3));
        }
        __stcs(Mr + i, mn);                       // M: evict-first
        Rhr[2 * i]     = __floats2bfloat162_rn(r.x, r.y);
        Rhr[2 * i + 1] = __floats2bfloat162_rn(r.z, r.w);
    }
}

extern "C" void kernel_launch(void* const* d_in, const int* in_sizes, int n_in,
                              void* d_out, int out_size) {
    const float* x          = (const float*)d_in[0];   // [B, D]
    const float* weights    = (const float*)d_in[1];   // [N, D]
    const float* moving_avg = (const float*)d_in[2];   // [N, D]
    const float* relevances = (const float*)d_in[3];   // [N, D]
    // d_in[4] = wins (unused for output)
    const void*  neighbors  = d_in[5];                 // [N, N] bool (width auto-detected)

    float* W = (float*)d_out;

    void* pM = nullptr;
    cudaGetSymbolAddress(&pM, g_M);

    const size_t bytes = sizeof(float) * (size_t)N_NODES * D_DIM;
    cudaMemcpyAsync(W,  weights,    bytes, cudaMemcpyDeviceToDevice);
    cudaMemcpyAsync(pM, moving_avg, bytes, cudaMemcpyDeviceToDevice);

    reset_best_kernel<<<1, 64>>>((const unsigned int*)neighbors);
    conv_kernel<<<(N_NODES * D_DIM / 4) / 256, 256>>>(weights, relevances);

    for (int t = 0; t < B_SAMP; t++) {
        const float* xt = x + (size_t)t * D_DIM;
        act_kernel<<<N_NODES, 256>>>(xt, t);
        update_kernel<<<N_NODES, 128>>>(xt, W, neighbors, t);
    }
}

// round 17
// speedup vs baseline: 1.1274x; 1.0129x over previous
#include <cuda_runtime.h>
#include <cuda_bf16.h>

#define N_NODES 4096
#define D_DIM   2048
#define B_SAMP  64

#define A_T_C    0.3f
#define DSBETA_C 1e-4f
#define E_B_C    0.5f
#define E_N_C    0.005f      // 0.01 * E_B
#define EPS_DS_C 0.01f

// Persistent state (allocation-free scratch).
// f32 R is NOT stored: R only feeds activations, which use the bf16 shadows.
__device__ float          g_M [(size_t)N_NODES * D_DIM];
__device__ __nv_bfloat162 g_Wh[(size_t)N_NODES * D_DIM / 2];   // bf16 shadow of W
__device__ __nv_bfloat162 g_Rh[(size_t)N_NODES * D_DIM / 2];   // bf16 shadow of R
__device__ unsigned long long g_best[B_SAMP];
__device__ int g_nb_word32;   // 1 => neighbors stored as 32-bit words, 0 => bytes

__global__ void reset_best_kernel(const unsigned int* __restrict__ nb) {
    if (threadIdx.x < B_SAMP) g_best[threadIdx.x] = 0ULL;
    if (threadIdx.x == 0) {
        // Bool widened to int32 -> words are 0/1; to float32 -> 0/0x3F800000.
        // Raw byte-bools give random packed words; P(all 256 pass) ~ (1/8)^256.
        int w32 = 1;
        for (int i = 0; i < 256; i++) {
            unsigned v = nb[i];
            if (!(v == 0u || v == 1u || v == 0x3F800000u)) { w32 = 0; break; }
        }
        g_nb_word32 = w32;
    }
}

// Convert initial W / R (f32) into the bf16 shadow arrays (8B packed stores).
__global__ __launch_bounds__(256) void conv_kernel(const float* __restrict__ Wf,
                                                   const float* __restrict__ Rf) {
    const size_t i = (size_t)blockIdx.x * 256 + threadIdx.x;   // float4 index
    float4 w = ((const float4*)Wf)[i];
    float4 r = ((const float4*)Rf)[i];
    __nv_bfloat162 w0 = __floats2bfloat162_rn(w.x, w.y);
    __nv_bfloat162 w1 = __floats2bfloat162_rn(w.z, w.w);
    __nv_bfloat162 r0 = __floats2bfloat162_rn(r.x, r.y);
    __nv_bfloat162 r1 = __floats2bfloat162_rn(r.z, r.w);
    uint2 uw; uw.x = *(unsigned*)&w0; uw.y = *(unsigned*)&w1;
    uint2 ur; ur.x = *(unsigned*)&r0; ur.y = *(unsigned*)&r1;
    ((uint2*)g_Wh)[i] = uw;
    ((uint2*)g_Rh)[i] = ur;
}

__device__ __forceinline__ void act_reduce_commit(float dist, float rsum,
                                                  int n, int slot,
                                                  float* sA, float* sB) {
    const int tid = threadIdx.x, wrp = tid >> 5, lane = tid & 31;
#pragma unroll
    for (int o = 16; o > 0; o >>= 1) {
        dist += __shfl_down_sync(0xffffffffu, dist, o);
        rsum += __shfl_down_sync(0xffffffffu, rsum, o);
    }
    if (lane == 0) { sA[wrp] = dist; sB[wrp] = rsum; }
    __syncthreads();
    if (tid == 0) {
        float dt = 0.f, rt = 0.f;
#pragma unroll
        for (int i = 0; i < 8; i++) { dt += sA[i]; rt += sB[i]; }
        float act = rt / (rt + dt + 1e-7f);
        // act > 0 so the float bit pattern is order-preserving. Low word =
        // 0xFFFFFFFF - n: ties pick the SMALLEST node index (jnp.argmax
        // first-occurrence semantics).
        unsigned long long key =
            ((unsigned long long)__float_as_uint(act) << 32) |
            (unsigned long long)(0xFFFFFFFFu - (unsigned)n);
        unsigned long long cur = g_best[slot];
        if (key > cur) atomicMax(&g_best[slot], key);
    }
}

// Step-0 activation from bf16 shadows. One block per node.
__global__ __launch_bounds__(256) void act_kernel(const float* __restrict__ x,
                                                  int slot) {
    const int n = blockIdx.x, tid = threadIdx.x;
    __shared__ float sA[8], sB[8];
    uint4 wv = ((const uint4*)(g_Wh + (size_t)n * (D_DIM / 2)))[tid];
    uint4 rv = ((const uint4*)(g_Rh + (size_t)n * (D_DIM / 2)))[tid];
    float4 x0 = __ldg(((const float4*)x) + 2 * tid);
    float4 x1 = __ldg(((const float4*)x) + 2 * tid + 1);

    float dist = 0.f, rsum = 0.f;
    float2 w0 = __bfloat1622float2(*(const __nv_bfloat162*)&wv.x);
    float2 w1 = __bfloat1622float2(*(const __nv_bfloat162*)&wv.y);
    float2 w2 = __bfloat1622float2(*(const __nv_bfloat162*)&wv.z);
    float2 w3 = __bfloat1622float2(*(const __nv_bfloat162*)&wv.w);
    float2 r0 = __bfloat1622float2(*(const __nv_bfloat162*)&rv.x);
    float2 r1 = __bfloat1622float2(*(const __nv_bfloat162*)&rv.y);
    float2 r2 = __bfloat1622float2(*(const __nv_bfloat162*)&rv.z);
    float2 r3 = __bfloat1622float2(*(const __nv_bfloat162*)&rv.w);
    float d;
    d = x0.x - w0.x; dist += r0.x * d * d;
    d = x0.y - w0.y; dist += r0.y * d * d;
    d = x0.z - w1.x; dist += r1.x * d * d;
    d = x0.w - w1.y; dist += r1.y * d * d;
    d = x1.x - w2.x; dist += r2.x * d * d;
    d = x1.y - w2.y; dist += r2.y * d * d;
    d = x1.z - w3.x; dist += r3.x * d * d;
    d = x1.w - w3.y; dist += r3.y * d * d;
    rsum = r0.x + r0.y + r1.x + r1.y + r2.x + r2.y + r3.x + r3.y;

    act_reduce_commit(dist, rsum, n, slot, sA, sB);
}

// Fused step: update(t) for winner+neighbors (exact f32 W/M), then act(t+1)
// for ALL rows. Touched rows feed act straight from registers (the freshly
// bf16-rounded w/r), untouched rows read their 8 KB shadow row.
__global__ __launch_bounds__(256) void fused_kernel(const float* __restrict__ x,
                                                    float* __restrict__ W,
                                                    const void* __restrict__ nbv,
                                                    int t, int do_act) {
    const int n = blockIdx.x, tid = threadIdx.x;
    const int wrp = tid >> 5, lane = tid & 31;
    __shared__ float sA[8], sB[8], sC[8];
    __shared__ float s_av, s_den;

    const unsigned long long key = g_best[t];
    const float pact = __uint_as_float((unsigned)(key >> 32));
    float lr = 0.f;
    if (pact >= A_T_C) {   // else do_upd == false -> no row is updated
        const int winner = (int)(0xFFFFFFFFu - (unsigned)(key & 0xFFFFFFFFu));
        if (n == winner) {
            lr = E_B_C;
        } else {
            const size_t idx = (size_t)winner * N_NODES + n;
            bool isnb = g_nb_word32 ? (__ldcs((const unsigned int*)nbv + idx) != 0u)
                                    : (__ldcs((const unsigned char*)nbv + idx) != 0);
            if (isnb) lr = E_N_C;
        }
    }

    const float* xu = x + (size_t)t * D_DIM;
    const float* xa = xu + D_DIM;              // sample t+1 (read only if do_act)

    float dist = 0.f, rsum = 0.f;

    if (lr > 0.f) {
        // ------- update path (exact f32 arithmetic) -------
        float4* Wr = (float4*)(W   + (size_t)n * D_DIM);
        float4* Mr = (float4*)(g_M + (size_t)n * D_DIM);
        uint2*  Whr = (uint2*)(g_Wh + (size_t)n * (D_DIM / 2));
        uint2*  Rhr = (uint2*)(g_Rh + (size_t)n * (D_DIM / 2));
        const float4* xur = (const float4*)xu;
        const float4* xar = (const float4*)xa;
        const float c = lr * DSBETA_C, omc = 1.0f - c;

        // prefetch everything (max MLP before any compute)
        float4 w0  = Wr[tid],            w1  = Wr[256 + tid];
        float4 m0  = __ldcs(Mr + tid),   m1  = __ldcs(Mr + 256 + tid);
        float4 xu0 = __ldg(xur + tid),   xu1 = __ldg(xur + 256 + tid);
        float4 xa0, xa1;
        if (do_act) { xa0 = __ldg(xar + tid); xa1 = __ldg(xar + 256 + tid); }

        float4 mn0, mn1, wn0, wn1;
        {
            float d0 = xu0.x - w0.x, d1 = xu0.y - w0.y, d2 = xu0.z - w0.z, d3 = xu0.w - w0.w;
            mn0.x = c * fabsf(d0) + omc * m0.x;
            mn0.y = c * fabsf(d1) + omc * m0.y;
            mn0.z = c * fabsf(d2) + omc * m0.z;
            mn0.w = c * fabsf(d3) + omc * m0.w;
            wn0.x = w0.x + lr * d0; wn0.y = w0.y + lr * d1;
            wn0.z = w0.z + lr * d2; wn0.w = w0.w + lr * d3;
        }
        {
            float d0 = xu1.x - w1.x, d1 = xu1.y - w1.y, d2 = xu1.z - w1.z, d3 = xu1.w - w1.w;
            mn1.x = c * fabsf(d0) + omc * m1.x;
            mn1.y = c * fabsf(d1) + omc * m1.y;
            mn1.z = c * fabsf(d2) + omc * m1.z;
            mn1.w = c * fabsf(d3) + omc * m1.w;
            wn1.x = w1.x + lr * d0; wn1.y = w1.y + lr * d1;
            wn1.z = w1.z + lr * d2; wn1.w = w1.w + lr * d3;
        }
        // W f32 + bf16 shadow: independent of the reduction -> store now
        Wr[tid]       = wn0;
        Wr[256 + tid] = wn1;
        __nv_bfloat162 wp0 = __floats2bfloat162_rn(wn0.x, wn0.y);
        __nv_bfloat162 wp1 = __floats2bfloat162_rn(wn0.z, wn0.w);
        __nv_bfloat162 wp2 = __floats2bfloat162_rn(wn1.x, wn1.y);
        __nv_bfloat162 wp3 = __floats2bfloat162_rn(wn1.z, wn1.w);
        uint2 uw0; uw0.x = *(unsigned*)&wp0; uw0.y = *(unsigned*)&wp1;
        uint2 uw1; uw1.x = *(unsigned*)&wp2; uw1.y = *(unsigned*)&wp3;
        Whr[tid]       = uw0;
        Whr[256 + tid] = uw1;

        // 3-way block reduction over M_new (max, min, sum)
        float pmax = fmaxf(fmaxf(fmaxf(mn0.x, mn0.y), fmaxf(mn0.z, mn0.w)),
                           fmaxf(fmaxf(mn1.x, mn1.y), fmaxf(mn1.z, mn1.w)));
        float pmin = fminf(fminf(fminf(mn0.x, mn0.y), fminf(mn0.z, mn0.w)),
                           fminf(fminf(mn1.x, mn1.y), fminf(mn1.z, mn1.w)));
        float psum = mn0.x + mn0.y + mn0.z + mn0.w + mn1.x + mn1.y + mn1.z + mn1.w;
#pragma unroll
        for (int o = 16; o > 0; o >>= 1) {
            pmax = fmaxf(pmax, __shfl_down_sync(0xffffffffu, pmax, o));
            pmin = fminf(pmin, __shfl_down_sync(0xffffffffu, pmin, o));
            psum +=            __shfl_down_sync(0xffffffffu, psum, o);
        }
        if (lane == 0) { sA[wrp] = pmax; sB[wrp] = pmin; sC[wrp] = psum; }
        __syncthreads();
        if (tid == 0) {
            float mx = -1e30f, mnv = 1e30f, sum = 0.f;
#pragma unroll
            for (int i = 0; i < 8; i++) {
                mx  = fmaxf(mx, sA[i]);
                mnv = fminf(mnv, sB[i]);
                sum += sC[i];
            }
            s_av  = sum / (float)D_DIM;
            s_den = EPS_DS_C * (mx - mnv);
        }
        __syncthreads();
        const float av = s_av, den = s_den;

        float4 r0v, r1v;
        if (den == 0.0f) {
            r0v.x = r0v.y = r0v.z = r0v.w = 1.0f;   // reference's NaN -> 1 path
            r1v = r0v;
        } else {
            float a0 = fminf(fmaxf((mn0.x - av) / den, -80.0f), 80.0f);
            float a1 = fminf(fmaxf((mn0.y - av) / den, -80.0f), 80.0f);
            float a2 = fminf(fmaxf((mn0.z - av) / den, -80.0f), 80.0f);
            float a3 = fminf(fmaxf((mn0.w - av) / den, -80.0f), 80.0f);
            float a4 = fminf(fmaxf((mn1.x - av) / den, -80.0f), 80.0f);
            float a5 = fminf(fmaxf((mn1.y - av) / den, -80.0f), 80.0f);
            float a6 = fminf(fmaxf((mn1.z - av) / den, -80.0f), 80.0f);
            float a7 = fminf(fmaxf((mn1.w - av) / den, -80.0f), 80.0f);
            // __expf error (~2^-21) is far below the bf16 rounding applied to
            // R's shadow, and R is consumed ONLY via the bf16 shadow.
            r0v.x = 1.0f / (1.0f + __expf(a0));
            r0v.y = 1.0f / (1.0f + __expf(a1));
            r0v.z = 1.0f / (1.0f + __expf(a2));
            r0v.w = 1.0f / (1.0f + __expf(a3));
            r1v.x = 1.0f / (1.0f + __expf(a4));
            r1v.y = 1.0f / (1.0f + __expf(a5));
            r1v.z = 1.0f / (1.0f + __expf(a6));
            r1v.w = 1.0f / (1.0f + __expf(a7));
        }
        __stcs(Mr + tid,       mn0);
        __stcs(Mr + 256 + tid, mn1);
        __nv_bfloat162 rp0 = __floats2bfloat162_rn(r0v.x, r0v.y);
        __nv_bfloat162 rp1 = __floats2bfloat162_rn(r0v.z, r0v.w);
        __nv_bfloat162 rp2 = __floats2bfloat162_rn(r1v.x, r1v.y);
        __nv_bfloat162 rp3 = __floats2bfloat162_rn(r1v.z, r1v.w);
        uint2 ur0; ur0.x = *(unsigned*)&rp0; ur0.y = *(unsigned*)&rp1;
        uint2 ur1; ur1.x = *(unsigned*)&rp2; ur1.y = *(unsigned*)&rp3;
        Rhr[tid]       = ur0;
        Rhr[256 + tid] = ur1;

        if (!do_act) return;

        // ------- act(t+1) from the bf16-rounded registers -------
        __syncthreads();   // protect sA/sB reuse across the block
        float2 f; float d;
        f = __bfloat1622float2(*(__nv_bfloat162*)&uw0.x);
        float2 g = __bfloat1622float2(*(__nv_bfloat162*)&ur0.x);
        d = xa0.x - f.x; dist += g.x * d * d;
        d = xa0.y - f.y; dist += g.y * d * d;
        rsum += g.x + g.y;
        f = __bfloat1622float2(*(__nv_bfloat162*)&uw0.y);
        g = __bfloat1622float2(*(__nv_bfloat162*)&ur0.y);
        d = xa0.z - f.x; dist += g.x * d * d;
        d = xa0.w - f.y; dist += g.y * d * d;
        rsum += g.x + g.y;
        f = __bfloat1622float2(*(__nv_bfloat162*)&uw1.x);
        g = __bfloat1622float2(*(__nv_bfloat162*)&ur1.x);
        d = xa1.x - f.x; dist += g.x * d * d;
        d = xa1.y - f.y; dist += g.y * d * d;
        rsum += g.x + g.y;
        f = __bfloat1622float2(*(__nv_bfloat162*)&uw1.y);
        g = __bfloat1622float2(*(__nv_bfloat162*)&ur1.y);
        d = xa1.z - f.x; dist += g.x * d * d;
        d = xa1.w - f.y; dist += g.y * d * d;
        rsum += g.x + g.y;
    } else {
        // ------- untouched row: act(t+1) from the stored shadows -------
        if (!do_act) return;
        uint4 wv = ((const uint4*)(g_Wh + (size_t)n * (D_DIM / 2)))[tid];
        uint4 rv = ((const uint4*)(g_Rh + (size_t)n * (D_DIM / 2)))[tid];
        float4 x0 = __ldg(((const float4*)xa) + 2 * tid);
        float4 x1 = __ldg(((const float4*)xa) + 2 * tid + 1);
        float2 w0 = __bfloat1622float2(*(const __nv_bfloat162*)&wv.x);
        float2 w1 = __bfloat1622float2(*(const __nv_bfloat162*)&wv.y);
        float2 w2 = __bfloat1622float2(*(const __nv_bfloat162*)&wv.z);
        float2 w3 = __bfloat1622float2(*(const __nv_bfloat162*)&wv.w);
        float2 r0 = __bfloat1622float2(*(const __nv_bfloat162*)&rv.x);
        float2 r1 = __bfloat1622float2(*(const __nv_bfloat162*)&rv.y);
        float2 r2 = __bfloat1622float2(*(const __nv_bfloat162*)&rv.z);
        float2 r3 = __bfloat1622float2(*(const __nv_bfloat162*)&rv.w);
        float d;
        d = x0.x - w0.x; dist += r0.x * d * d;
        d = x0.y - w0.y; dist += r0.y * d * d;
        d = x0.z - w1.x; dist += r1.x * d * d;
        d = x0.w - w1.y; dist += r1.y * d * d;
        d = x1.x - w2.x; dist += r2.x * d * d;
        d = x1.y - w2.y; dist += r2.y * d * d;
        d = x1.z - w3.x; dist += r3.x * d * d;
        d = x1.w - w3.y; dist += r3.y * d * d;
        rsum = r0.x + r0.y + r1.x + r1.y + r2.x + r2.y + r3.x + r3.y;
    }

    act_reduce_commit(dist, rsum, n, t + 1, sA, sB);
}

extern "C" void kernel_launch(void* const* d_in, const int* in_sizes, int n_in,
                              void* d_out, int out_size) {
    const float* x          = (const float*)d_in[0];   // [B, D]
    const float* weights    = (const float*)d_in[1];   // [N, D]
    const float* moving_avg = (const float*)d_in[2];   // [N, D]
    const float* relevances = (const float*)d_in[3];   // [N, D]
    // d_in[4] = wins (unused for output)
    const void*  neighbors  = d_in[5];                 // [N, N] bool (width auto-detected)

    float* W = (float*)d_out;

    void* pM = nullptr;
    cudaGetSymbolAddress(&pM, g_M);

    const size_t bytes = sizeof(float) * (size_t)N_NODES * D_DIM;
    cudaMemcpyAsync(W,  weights,    bytes, cudaMemcpyDeviceToDevice);
    cudaMemcpyAsync(pM, moving_avg, bytes, cudaMemcpyDeviceToDevice);

    reset_best_kernel<<<1, 64>>>((const unsigned int*)neighbors);
    conv_kernel<<<(N_NODES * D_DIM / 4) / 256, 256>>>(weights, relevances);

    act_kernel<<<N_NODES, 256>>>(x, 0);
    for (int t = 0; t < B_SAMP; t++) {
        fused_kernel<<<N_NODES, 256>>>(x, W, neighbors, t,
                                       (t + 1 < B_SAMP) ? 1 : 0);
    }
}